// round 1
// baseline (speedup 1.0000x reference)
#include <cuda_runtime.h>

#define B_  4
#define L_  4096
#define H_  16
#define D_  128
#define C_  64
#define NC_ 64
#define GATING_Cf 8.0f

// Scratch (allocation-free rule: __device__ globals)
__device__ float g_final_h[B_ * NC_ * H_ * 2 * D_];   // (b,nc,h,s,d)
__device__ float g_total_A[B_ * NC_ * H_ * 4];        // (b,nc,h,{a00,a01,a10,a11})

// ---------------------------------------------------------------------------
// Per-timestep scalar precompute (Cayley discretization + gate modulation).
// Block covers 4 heads (one per warp) x 64 timesteps of one chunk.
// sA[wi*64+t] = {a11, a12, beta, beta*dt*v0}; sC1[wi*64+t] = beta*dt*v1
// ---------------------------------------------------------------------------
__device__ __forceinline__ void precompute_scalars(
    int b, int nc, int hbase,
    const float* __restrict__ alpha, const float* __restrict__ omega,
    const float* __restrict__ dt,    const float* __restrict__ beta,
    const float* __restrict__ rg,    const float* __restrict__ V,
    float4* sA, float* sC1)
{
    for (int q = threadIdx.x; q < 4 * C_; q += blockDim.x) {
        int wi = q >> 6;
        int t  = q & 63;
        int h  = hbase + wi;
        int l  = nc * C_ + t;
        int idx = (b * L_ + l) * H_ + h;

        float al  = alpha[idx];
        float om  = omega[idx];
        float dtt = dt[idx];
        float be  = beta[idx];
        float r   = rg[idx];

        float tau = 0.5f * dtt;
        float ta  = tau * al;
        float to  = tau * om;
        float opa = 1.0f + ta;
        float oma = 1.0f - ta;
        float to2 = to * to;

        float den   = opa * opa + to2 + 1e-6f;
        float invd  = 1.0f / den;
        float a11   = (opa * oma - to2) * invd;
        float a12   = 2.0f * to * invd;

        float numer = oma * oma + to2;
        float den_e = opa * opa + to2;
        float eig   = numer / (den_e + 1e-6f);
        float expo  = (GATING_Cf * r - 1.0f) * 0.5f;
        float scale = powf(fmaxf(eig, 1e-8f), expo);
        a11 *= scale;
        a12 *= scale;

        float v0  = V[idx * 2 + 0];
        float v1  = V[idx * 2 + 1];
        float bdt = be * dtt;

        sA[q]  = make_float4(a11, a12, be, bdt * v0);
        sC1[q] = bdt * v1;
    }
}

// ---------------------------------------------------------------------------
// K1: intra-chunk scan -> final_h (2xD) and total_A (2x2) per (b,nc,h).
// One warp per (b,nc,h); lane owns 4 d-slots. Dot product via shfl butterfly.
// ---------------------------------------------------------------------------
__global__ __launch_bounds__(128)
void k_intra(const float* __restrict__ alpha, const float* __restrict__ omega,
             const float* __restrict__ dt,    const float* __restrict__ K,
             const float* __restrict__ V,     const float* __restrict__ beta,
             const float* __restrict__ rg)
{
    __shared__ float4 sA[4 * C_];
    __shared__ float  sC1[4 * C_];

    int blk   = blockIdx.x;          // ((b*NC + nc)*4 + hg)
    int hg    = blk & 3;
    int bn    = blk >> 2;
    int nc    = bn % NC_;
    int b     = bn / NC_;
    int hbase = hg * 4;

    precompute_scalars(b, nc, hbase, alpha, omega, dt, beta, rg, V, sA, sC1);
    __syncthreads();

    int wi   = threadIdx.x >> 5;
    int lane = threadIdx.x & 31;
    int h    = hbase + wi;

    float h0[4] = {0.f, 0.f, 0.f, 0.f};
    float h1[4] = {0.f, 0.f, 0.f, 0.f};
    float A00 = 1.f, A01 = 0.f, A10 = 0.f, A11 = 1.f;

    const float4* Kp = (const float4*)K + ((b * L_ + nc * C_) * H_ + h) * (D_ / 4) + lane;
    const int kstride = H_ * (D_ / 4);

    #pragma unroll 2
    for (int t = 0; t < C_; t++) {
        float4 kv = Kp[t * kstride];
        float4 sc = sA[wi * C_ + t];
        float  c1 = sC1[wi * C_ + t];

        float p0 = h0[0]*kv.x + h0[1]*kv.y + h0[2]*kv.z + h0[3]*kv.w;
        float p1 = h1[0]*kv.x + h1[1]*kv.y + h1[2]*kv.z + h1[3]*kv.w;
        #pragma unroll
        for (int o = 16; o; o >>= 1) {
            p0 += __shfl_xor_sync(0xffffffffu, p0, o);
            p1 += __shfl_xor_sync(0xffffffffu, p1, o);
        }
        float b0 = sc.z * p0;
        float b1 = sc.z * p1;

        float kk[4] = {kv.x, kv.y, kv.z, kv.w};
        #pragma unroll
        for (int j = 0; j < 4; j++) {
            float hm0 = fmaf(-b0, kk[j], h0[j]);
            float hm1 = fmaf(-b1, kk[j], h1[j]);
            h0[j] = sc.x * hm0 + sc.y * hm1 + sc.w * kk[j];
            h1[j] = sc.x * hm1 - sc.y * hm0 + c1   * kk[j];
        }
        // cumA = A_t @ cumA
        float n00 = sc.x * A00 + sc.y * A10;
        float n01 = sc.x * A01 + sc.y * A11;
        float n10 = sc.x * A10 - sc.y * A00;
        float n11 = sc.x * A11 - sc.y * A01;
        A00 = n00; A01 = n01; A10 = n10; A11 = n11;
    }

    int base = (((b * NC_ + nc) * H_ + h) * 2) * D_;
    ((float4*)&g_final_h[base])[lane]       = make_float4(h0[0], h0[1], h0[2], h0[3]);
    ((float4*)&g_final_h[base + D_])[lane]  = make_float4(h1[0], h1[1], h1[2], h1[3]);
    if (lane == 0)
        ((float4*)g_total_A)[(b * NC_ + nc) * H_ + h] = make_float4(A00, A01, A10, A11);
}

// ---------------------------------------------------------------------------
// K2: inter-chunk serial scan. One block per (b,h), thread = d.
// Emits the PRE-update state (state entering chunk nc) to out_states.
// Depth-1 software prefetch of A / final_h.
// ---------------------------------------------------------------------------
__global__ __launch_bounds__(128)
void k_inter(float* __restrict__ out_states)
{
    int b = blockIdx.x >> 4;
    int h = blockIdx.x & 15;
    int d = threadIdx.x;

    float s0 = 0.f, s1 = 0.f;

    float4 a  = ((const float4*)g_total_A)[(b * NC_ + 0) * H_ + h];
    int fb    = (((b * NC_ + 0) * H_ + h) * 2) * D_;
    float f0  = g_final_h[fb + d];
    float f1  = g_final_h[fb + D_ + d];

    for (int nc = 0; nc < NC_; nc++) {
        float4 an = make_float4(0.f, 0.f, 0.f, 0.f);
        float f0n = 0.f, f1n = 0.f;
        if (nc + 1 < NC_) {
            an = ((const float4*)g_total_A)[(b * NC_ + nc + 1) * H_ + h];
            int fb2 = (((b * NC_ + nc + 1) * H_ + h) * 2) * D_;
            f0n = g_final_h[fb2 + d];
            f1n = g_final_h[fb2 + D_ + d];
        }
        int ob = (((b * NC_ + nc) * H_ + h) * 2) * D_;
        out_states[ob + d]       = s0;
        out_states[ob + D_ + d]  = s1;

        float ns0 = a.x * s0 + a.y * s1 + f0;
        float ns1 = a.z * s0 + a.w * s1 + f1;
        s0 = ns0; s1 = ns1;
        a = an; f0 = f0n; f1 = f1n;
    }
}

// ---------------------------------------------------------------------------
// K3: full pass. Re-runs the intra scan, tracks g = cumA_t @ state0
// incrementally, writes Y = h_t + g_t.
// ---------------------------------------------------------------------------
__global__ __launch_bounds__(128)
void k_full(const float* __restrict__ alpha, const float* __restrict__ omega,
            const float* __restrict__ dt,    const float* __restrict__ K,
            const float* __restrict__ V,     const float* __restrict__ beta,
            const float* __restrict__ rg,    const float* __restrict__ states,
            float* __restrict__ Y)
{
    __shared__ float4 sA[4 * C_];
    __shared__ float  sC1[4 * C_];

    int blk   = blockIdx.x;
    int hg    = blk & 3;
    int bn    = blk >> 2;
    int nc    = bn % NC_;
    int b     = bn / NC_;
    int hbase = hg * 4;

    precompute_scalars(b, nc, hbase, alpha, omega, dt, beta, rg, V, sA, sC1);
    __syncthreads();

    int wi   = threadIdx.x >> 5;
    int lane = threadIdx.x & 31;
    int h    = hbase + wi;

    // chunk entering state -> correction tracker g
    int sb = (((b * NC_ + nc) * H_ + h) * 2) * D_;
    float4 g0v = ((const float4*)&states[sb])[lane];
    float4 g1v = ((const float4*)&states[sb + D_])[lane];
    float g0[4] = {g0v.x, g0v.y, g0v.z, g0v.w};
    float g1[4] = {g1v.x, g1v.y, g1v.z, g1v.w};

    float h0[4] = {0.f, 0.f, 0.f, 0.f};
    float h1[4] = {0.f, 0.f, 0.f, 0.f};

    const float4* Kp = (const float4*)K + ((b * L_ + nc * C_) * H_ + h) * (D_ / 4) + lane;
    const int kstride = H_ * (D_ / 4);
    int ybase = (((b * L_ + nc * C_) * H_ + h) * 2) * D_;
    const int ystride = H_ * 2 * D_;

    #pragma unroll 2
    for (int t = 0; t < C_; t++) {
        float4 kv = Kp[t * kstride];
        float4 sc = sA[wi * C_ + t];
        float  c1 = sC1[wi * C_ + t];

        float p0 = h0[0]*kv.x + h0[1]*kv.y + h0[2]*kv.z + h0[3]*kv.w;
        float p1 = h1[0]*kv.x + h1[1]*kv.y + h1[2]*kv.z + h1[3]*kv.w;
        #pragma unroll
        for (int o = 16; o; o >>= 1) {
            p0 += __shfl_xor_sync(0xffffffffu, p0, o);
            p1 += __shfl_xor_sync(0xffffffffu, p1, o);
        }
        float b0 = sc.z * p0;
        float b1 = sc.z * p1;

        float kk[4] = {kv.x, kv.y, kv.z, kv.w};
        float y0[4], y1[4];
        #pragma unroll
        for (int j = 0; j < 4; j++) {
            float hm0 = fmaf(-b0, kk[j], h0[j]);
            float hm1 = fmaf(-b1, kk[j], h1[j]);
            h0[j] = sc.x * hm0 + sc.y * hm1 + sc.w * kk[j];
            h1[j] = sc.x * hm1 - sc.y * hm0 + c1   * kk[j];
            // g = A_t @ g   (correction = cumA_t @ state0)
            float n0 = sc.x * g0[j] + sc.y * g1[j];
            float n1 = sc.x * g1[j] - sc.y * g0[j];
            g0[j] = n0; g1[j] = n1;
            y0[j] = h0[j] + g0[j];
            y1[j] = h1[j] + g1[j];
        }
        ((float4*)&Y[ybase + t * ystride])[lane]      = make_float4(y0[0], y0[1], y0[2], y0[3]);
        ((float4*)&Y[ybase + t * ystride + D_])[lane] = make_float4(y1[0], y1[1], y1[2], y1[3]);
    }
}

// ---------------------------------------------------------------------------
extern "C" void kernel_launch(void* const* d_in, const int* in_sizes, int n_in,
                              void* d_out, int out_size)
{
    const float* alpha = (const float*)d_in[0];
    const float* omega = (const float*)d_in[1];
    const float* dt    = (const float*)d_in[2];
    const float* K     = (const float*)d_in[3];
    const float* V     = (const float*)d_in[4];
    const float* beta  = (const float*)d_in[5];
    const float* rg    = (const float*)d_in[6];

    float* Y      = (float*)d_out;                       // (B,L,H,2,D)
    float* states = Y + (size_t)B_ * L_ * H_ * 2 * D_;   // (B,NC,H,2,D)

    k_intra<<<B_ * NC_ * (H_ / 4), 128>>>(alpha, omega, dt, K, V, beta, rg);
    k_inter<<<B_ * H_, 128>>>(states);
    k_full<<<B_ * NC_ * (H_ / 4), 128>>>(alpha, omega, dt, K, V, beta, rg, states, Y);
}

// round 3
// speedup vs baseline: 1.0636x; 1.0636x over previous
#include <cuda_runtime.h>

#define B_  4
#define L_  4096
#define H_  16
#define D_  128
#define C_  64
#define NC_ 64
#define GATING_Cf 8.0f

// Scratch (allocation-free rule: __device__ globals)
__device__ float g_final_h[B_ * NC_ * H_ * 2 * D_];   // (b,nc,h,s,d)
__device__ float g_total_A[B_ * NC_ * H_ * 4];        // (b,nc,h,{a00,a01,a10,a11})
__device__ float g_u[B_ * NC_ * H_ * C_ * 2];         // (b,nc,h,t,{u0,u1})

// ---------------------------------------------------------------------------
// Per-timestep scalar precompute (Cayley discretization + gate modulation).
// sA[wi*64+t] = {a11, a12, beta, beta*dt*v0}; sC1[wi*64+t] = beta*dt*v1
// ---------------------------------------------------------------------------
__device__ __forceinline__ void precompute_scalars(
    int b, int nc, int hbase,
    const float* __restrict__ alpha, const float* __restrict__ omega,
    const float* __restrict__ dt,    const float* __restrict__ beta,
    const float* __restrict__ rg,    const float* __restrict__ V,
    float4* sA, float* sC1)
{
    for (int q = threadIdx.x; q < 4 * C_; q += blockDim.x) {
        int wi = q >> 6;
        int t  = q & 63;
        int h  = hbase + wi;
        int l  = nc * C_ + t;
        int idx = (b * L_ + l) * H_ + h;

        float al  = alpha[idx];
        float om  = omega[idx];
        float dtt = dt[idx];
        float be  = beta[idx];
        float r   = rg[idx];

        float tau = 0.5f * dtt;
        float ta  = tau * al;
        float to  = tau * om;
        float opa = 1.0f + ta;
        float oma = 1.0f - ta;
        float to2 = to * to;

        float den   = opa * opa + to2 + 1e-6f;
        float invd  = 1.0f / den;
        float a11   = (opa * oma - to2) * invd;
        float a12   = 2.0f * to * invd;

        float numer = oma * oma + to2;
        float den_e = opa * opa + to2;
        float eig   = numer / (den_e + 1e-6f);
        float expo  = (GATING_Cf * r - 1.0f) * 0.5f;
        float scale = exp2f(expo * __log2f(fmaxf(eig, 1e-8f)));
        a11 *= scale;
        a12 *= scale;

        float v0  = V[idx * 2 + 0];
        float v1  = V[idx * 2 + 1];
        float bdt = be * dtt;

        sA[q]  = make_float4(a11, a12, be, bdt * v0);
        sC1[q] = bdt * v1;
    }
}

// Lightweight variant for k_full: only (a11, a12) needed.
__device__ __forceinline__ void precompute_c_only(
    int b, int nc, int hbase,
    const float* __restrict__ alpha, const float* __restrict__ omega,
    const float* __restrict__ dt,    const float* __restrict__ rg,
    float2* sC)
{
    for (int q = threadIdx.x; q < 4 * C_; q += blockDim.x) {
        int wi = q >> 6;
        int t  = q & 63;
        int h  = hbase + wi;
        int l  = nc * C_ + t;
        int idx = (b * L_ + l) * H_ + h;

        float al  = alpha[idx];
        float om  = omega[idx];
        float dtt = dt[idx];
        float r   = rg[idx];

        float tau = 0.5f * dtt;
        float ta  = tau * al;
        float to  = tau * om;
        float opa = 1.0f + ta;
        float oma = 1.0f - ta;
        float to2 = to * to;

        float den   = opa * opa + to2 + 1e-6f;
        float invd  = 1.0f / den;
        float a11   = (opa * oma - to2) * invd;
        float a12   = 2.0f * to * invd;

        float numer = oma * oma + to2;
        float den_e = opa * opa + to2;
        float eig   = numer / (den_e + 1e-6f);
        float expo  = (GATING_Cf * r - 1.0f) * 0.5f;
        float scale = exp2f(expo * __log2f(fmaxf(eig, 1e-8f)));

        sC[q] = make_float2(a11 * scale, a12 * scale);
    }
}

// 5 simultaneous warp reductions (independent butterfly chains -> ILP)
__device__ __forceinline__ void warp_sum5(float& a, float& b, float& c,
                                          float& d, float& e) {
    #pragma unroll
    for (int o = 16; o; o >>= 1) {
        a += __shfl_xor_sync(0xffffffffu, a, o);
        b += __shfl_xor_sync(0xffffffffu, b, o);
        c += __shfl_xor_sync(0xffffffffu, c, o);
        d += __shfl_xor_sync(0xffffffffu, d, o);
        e += __shfl_xor_sync(0xffffffffu, e, o);
    }
}

// ---------------------------------------------------------------------------
// K1: intra-chunk scan, 2 timesteps per reduction round.
// Emits final_h, total_A (rotation scalar), and per-step u_t scalars.
// ---------------------------------------------------------------------------
__global__ __launch_bounds__(128)
void k_intra(const float* __restrict__ alpha, const float* __restrict__ omega,
             const float* __restrict__ dt,    const float* __restrict__ K,
             const float* __restrict__ V,     const float* __restrict__ beta,
             const float* __restrict__ rg)
{
    __shared__ float4 sA[4 * C_];
    __shared__ float  sC1[4 * C_];
    __shared__ float2 sU[4][C_];

    int blk   = blockIdx.x;          // ((b*NC + nc)*4 + hg)
    int hg    = blk & 3;
    int bn    = blk >> 2;
    int nc    = bn % NC_;
    int b     = bn / NC_;
    int hbase = hg * 4;

    precompute_scalars(b, nc, hbase, alpha, omega, dt, beta, rg, V, sA, sC1);
    __syncthreads();

    int wi   = threadIdx.x >> 5;
    int lane = threadIdx.x & 31;
    int h    = hbase + wi;

    float S0[4] = {0.f, 0.f, 0.f, 0.f};
    float S1[4] = {0.f, 0.f, 0.f, 0.f};
    float Ax = 1.f, Ay = 0.f;                 // cumA as rotation scalar

    const float4* Kp = (const float4*)K + ((b * L_ + nc * C_) * H_ + h) * (D_ / 4) + lane;
    const int kstride = H_ * (D_ / 4);

    #pragma unroll 2
    for (int i = 0; i < C_ / 2; i++) {
        int t  = 2 * i;
        int t1 = t + 1;
        float4 kv0 = Kp[t  * kstride];
        float4 kv1 = Kp[t1 * kstride];
        float4 s0  = sA[wi * C_ + t];    // {a11, a12, beta, w0}
        float4 s1  = sA[wi * C_ + t1];
        float  w0b = sC1[wi * C_ + t];   // w1 of step t
        float  w1b = sC1[wi * C_ + t1];  // w1 of step t1

        // 5 partial dots (vs S_{t-1}) + one Gram term
        float p10 = S0[0]*kv0.x + S0[1]*kv0.y + S0[2]*kv0.z + S0[3]*kv0.w;
        float p11 = S1[0]*kv0.x + S1[1]*kv0.y + S1[2]*kv0.z + S1[3]*kv0.w;
        float p20 = S0[0]*kv1.x + S0[1]*kv1.y + S0[2]*kv1.z + S0[3]*kv1.w;
        float p21 = S1[0]*kv1.x + S1[1]*kv1.y + S1[2]*kv1.z + S1[3]*kv1.w;
        float pg  = kv0.x*kv1.x + kv0.y*kv1.y + kv0.z*kv1.z + kv0.w*kv1.w;
        warp_sum5(p10, p11, p20, p21, pg);

        // u_t = w_t - beta_t * act(c_t, d1)
        float bd0 = s0.x * p10 + s0.y * p11;
        float bd1 = s0.x * p11 - s0.y * p10;
        float u00 = s0.w - s0.z * bd0;
        float u01 = w0b  - s0.z * bd1;

        // k_{t1}.S_t = act(c_t, d2) + g12 * u_t
        float q0 = s0.x * p20 + s0.y * p21 + pg * u00;
        float q1 = s0.x * p21 - s0.y * p20 + pg * u01;

        // u_{t1} = w_{t1} - beta_{t1} * act(c_{t1}, q)
        float r0  = s1.x * q0 + s1.y * q1;
        float r1  = s1.x * q1 - s1.y * q0;
        float u10 = s1.w - s1.z * r0;
        float u11 = w1b  - s1.z * r1;

        // e = c_{t1} * c_t  (complex mult, commutative)
        float ex = s1.x * s0.x - s1.y * s0.y;
        float ey = s1.x * s0.y + s1.y * s0.x;
        // f = act(c_{t1}, u_t)
        float f0 = s1.x * u00 + s1.y * u01;
        float f1 = s1.x * u01 - s1.y * u00;

        float kk0[4] = {kv0.x, kv0.y, kv0.z, kv0.w};
        float kk1[4] = {kv1.x, kv1.y, kv1.z, kv1.w};
        #pragma unroll
        for (int j = 0; j < 4; j++) {
            float o0 = S0[j];
            S0[j] = ex * S0[j] + ey * S1[j] + f0 * kk0[j] + u10 * kk1[j];
            S1[j] = ex * S1[j] - ey * o0    + f1 * kk0[j] + u11 * kk1[j];
        }

        // cumA update
        float nAx = ex * Ax - ey * Ay;
        float nAy = ex * Ay + ey * Ax;
        Ax = nAx; Ay = nAy;

        if (lane == 0) {
            sU[wi][t]  = make_float2(u00, u01);
            sU[wi][t1] = make_float2(u10, u11);
        }
    }

    int base = (((b * NC_ + nc) * H_ + h) * 2) * D_;
    ((float4*)&g_final_h[base])[lane]      = make_float4(S0[0], S0[1], S0[2], S0[3]);
    ((float4*)&g_final_h[base + D_])[lane] = make_float4(S1[0], S1[1], S1[2], S1[3]);
    if (lane == 0)
        ((float4*)g_total_A)[(b * NC_ + nc) * H_ + h] = make_float4(Ax, Ay, -Ay, Ax);

    __syncwarp();
    // coalesced u writeback: 64 t * 2 floats = 32 float4 per warp
    float4* ug = (float4*)&g_u[(((b * NC_ + nc) * H_ + h) * C_) * 2];
    ug[lane] = ((const float4*)sU[wi])[lane];
}

// ---------------------------------------------------------------------------
// K2: inter-chunk serial scan. One block per (b,h), thread = d.
// Emits the PRE-update state (state entering chunk nc).
// ---------------------------------------------------------------------------
__global__ __launch_bounds__(128)
void k_inter(float* __restrict__ out_states)
{
    int b = blockIdx.x >> 4;
    int h = blockIdx.x & 15;
    int d = threadIdx.x;

    float s0 = 0.f, s1 = 0.f;

    float4 a  = ((const float4*)g_total_A)[(b * NC_ + 0) * H_ + h];
    int fb    = (((b * NC_ + 0) * H_ + h) * 2) * D_;
    float f0  = g_final_h[fb + d];
    float f1  = g_final_h[fb + D_ + d];

    for (int nc = 0; nc < NC_; nc++) {
        float4 an = make_float4(0.f, 0.f, 0.f, 0.f);
        float f0n = 0.f, f1n = 0.f;
        if (nc + 1 < NC_) {
            an = ((const float4*)g_total_A)[(b * NC_ + nc + 1) * H_ + h];
            int fb2 = (((b * NC_ + nc + 1) * H_ + h) * 2) * D_;
            f0n = g_final_h[fb2 + d];
            f1n = g_final_h[fb2 + D_ + d];
        }
        int ob = (((b * NC_ + nc) * H_ + h) * 2) * D_;
        out_states[ob + d]       = s0;
        out_states[ob + D_ + d]  = s1;

        float ns0 = a.x * s0 + a.y * s1 + f0;
        float ns1 = a.z * s0 + a.w * s1 + f1;
        s0 = ns0; s1 = ns1;
        a = an; f0 = f0n; f1 = f1n;
    }
}

// ---------------------------------------------------------------------------
// K3: output pass. NO reductions: z_t = c_t * z_{t-1} + u_t * k_t,
// z_0 = chunk entering state; Y row t = z_t.
// ---------------------------------------------------------------------------
__global__ __launch_bounds__(128)
void k_full(const float* __restrict__ alpha, const float* __restrict__ omega,
            const float* __restrict__ dt,    const float* __restrict__ K,
            const float* __restrict__ rg,    const float* __restrict__ states,
            float* __restrict__ Y)
{
    __shared__ float2 sC[4 * C_];
    __shared__ float2 sU[4 * C_];

    int blk   = blockIdx.x;
    int hg    = blk & 3;
    int bn    = blk >> 2;
    int nc    = bn % NC_;
    int b     = bn / NC_;
    int hbase = hg * 4;

    precompute_c_only(b, nc, hbase, alpha, omega, dt, rg, sC);

    // load u for this block's 4 heads: 512 contiguous floats -> 128 float4
    {
        const float4* ug = (const float4*)&g_u[(((b * NC_ + nc) * H_ + hbase) * C_) * 2];
        float4 v = ug[threadIdx.x];
        int hi = threadIdx.x >> 5;          // 32 float4 per head
        int t2 = (threadIdx.x & 31) * 2;
        sU[hi * C_ + t2]     = make_float2(v.x, v.y);
        sU[hi * C_ + t2 + 1] = make_float2(v.z, v.w);
    }
    __syncthreads();

    int wi   = threadIdx.x >> 5;
    int lane = threadIdx.x & 31;
    int h    = hbase + wi;

    // init z = chunk entering state
    int sb = (((b * NC_ + nc) * H_ + h) * 2) * D_;
    float4 z0v = ((const float4*)&states[sb])[lane];
    float4 z1v = ((const float4*)&states[sb + D_])[lane];
    float z0[4] = {z0v.x, z0v.y, z0v.z, z0v.w};
    float z1[4] = {z1v.x, z1v.y, z1v.z, z1v.w};

    const float4* Kp = (const float4*)K + ((b * L_ + nc * C_) * H_ + h) * (D_ / 4) + lane;
    const int kstride = H_ * (D_ / 4);
    float4* Yp = (float4*)&Y[(((b * L_ + nc * C_) * H_ + h) * 2) * D_] + lane;
    const int ystride = H_ * 2 * (D_ / 4);

    #pragma unroll 4
    for (int t = 0; t < C_; t++) {
        float4 kv = __ldcs(&Kp[t * kstride]);
        float2 c  = sC[wi * C_ + t];
        float2 u  = sU[wi * C_ + t];

        float kk[4] = {kv.x, kv.y, kv.z, kv.w};
        #pragma unroll
        for (int j = 0; j < 4; j++) {
            float o0 = z0[j];
            z0[j] = c.x * z0[j] + c.y * z1[j] + u.x * kk[j];
            z1[j] = c.x * z1[j] - c.y * o0    + u.y * kk[j];
        }
        __stcs(&Yp[t * ystride],
               make_float4(z0[0], z0[1], z0[2], z0[3]));
        __stcs(&Yp[t * ystride + D_ / 4],
               make_float4(z1[0], z1[1], z1[2], z1[3]));
    }
}

// ---------------------------------------------------------------------------
extern "C" void kernel_launch(void* const* d_in, const int* in_sizes, int n_in,
                              void* d_out, int out_size)
{
    const float* alpha = (const float*)d_in[0];
    const float* omega = (const float*)d_in[1];
    const float* dt    = (const float*)d_in[2];
    const float* K     = (const float*)d_in[3];
    const float* V     = (const float*)d_in[4];
    const float* beta  = (const float*)d_in[5];
    const float* rg    = (const float*)d_in[6];

    float* Y      = (float*)d_out;                       // (B,L,H,2,D)
    float* states = Y + (size_t)B_ * L_ * H_ * 2 * D_;   // (B,NC,H,2,D)

    k_intra<<<B_ * NC_ * (H_ / 4), 128>>>(alpha, omega, dt, K, V, beta, rg);
    k_inter<<<B_ * H_, 128>>>(states);
    k_full<<<B_ * NC_ * (H_ / 4), 128>>>(alpha, omega, dt, K, rg, states, Y);
}

// round 4
// speedup vs baseline: 1.0675x; 1.0037x over previous
#include <cuda_runtime.h>

#define B_  4
#define L_  4096
#define H_  16
#define D_  128
#define C_  64
#define NC_ 64
#define GATING_Cf 8.0f

// Scratch (allocation-free rule: __device__ globals)
__device__ float  g_loc_h[B_ * NC_ * H_ * 2 * D_];
__device__ float  g_inc_h[B_ * NC_ * H_ * 2 * D_];
__device__ float2 g_loc_A[B_ * NC_ * H_];
__device__ int    g_flag[B_ * NC_ * H_];     // 0=none, 1=local, 2=inclusive

__device__ __forceinline__ int ld_acquire(const int* p) {
    int v;
    asm volatile("ld.acquire.gpu.global.b32 %0, [%1];" : "=r"(v) : "l"(p) : "memory");
    return v;
}
__device__ __forceinline__ void st_release(int* p, int v) {
    asm volatile("st.release.gpu.global.b32 [%0], %1;" :: "l"(p), "r"(v) : "memory");
}

__global__ void k_clear() {
    int i = blockIdx.x * blockDim.x + threadIdx.x;
    if (i < B_ * NC_ * H_) g_flag[i] = 0;
}

// ---------------------------------------------------------------------------
// Per-timestep scalar precompute (Cayley discretization + gate modulation).
// sA[wi*64+t] = {a11, a12, beta, beta*dt*v0}; sC1[wi*64+t] = beta*dt*v1
// ---------------------------------------------------------------------------
__device__ __forceinline__ void precompute_scalars(
    int b, int nc, int hbase,
    const float* __restrict__ alpha, const float* __restrict__ omega,
    const float* __restrict__ dt,    const float* __restrict__ beta,
    const float* __restrict__ rg,    const float* __restrict__ V,
    float4* sA, float* sC1)
{
    for (int q = threadIdx.x; q < 4 * C_; q += blockDim.x) {
        int wi = q >> 6;
        int t  = q & 63;
        int h  = hbase + wi;
        int l  = nc * C_ + t;
        int idx = (b * L_ + l) * H_ + h;

        float al  = alpha[idx];
        float om  = omega[idx];
        float dtt = dt[idx];
        float be  = beta[idx];
        float r   = rg[idx];

        float tau = 0.5f * dtt;
        float ta  = tau * al;
        float to  = tau * om;
        float opa = 1.0f + ta;
        float oma = 1.0f - ta;
        float to2 = to * to;

        float den   = opa * opa + to2 + 1e-6f;
        float invd  = 1.0f / den;
        float a11   = (opa * oma - to2) * invd;
        float a12   = 2.0f * to * invd;

        float numer = oma * oma + to2;
        float den_e = opa * opa + to2;
        float eig   = numer / (den_e + 1e-6f);
        float expo  = (GATING_Cf * r - 1.0f) * 0.5f;
        float scale = exp2f(expo * __log2f(fmaxf(eig, 1e-8f)));
        a11 *= scale;
        a12 *= scale;

        float v0  = V[idx * 2 + 0];
        float v1  = V[idx * 2 + 1];
        float bdt = be * dtt;

        sA[q]  = make_float4(a11, a12, be, bdt * v0);
        sC1[q] = bdt * v1;
    }
}

// ---------------------------------------------------------------------------
// Fused kernel: intra scan -> publish local -> lookback -> publish inclusive
// -> stream Y. One warp per (b,nc,h); lane owns 4 d-slots.
// ---------------------------------------------------------------------------
__global__ __launch_bounds__(128, 8)
void k_fused(const float* __restrict__ alpha, const float* __restrict__ omega,
             const float* __restrict__ dt,    const float* __restrict__ K,
             const float* __restrict__ V,     const float* __restrict__ beta,
             const float* __restrict__ rg,    float* __restrict__ Y,
             float* __restrict__ states)
{
    __shared__ float4 sA[4 * C_];
    __shared__ float  sC1[4 * C_];
    __shared__ float2 sU[4][C_];

    int blk   = blockIdx.x;          // ((b*NC + nc)*4 + hg)
    int hg    = blk & 3;
    int bn    = blk >> 2;
    int nc    = bn % NC_;
    int b     = bn / NC_;
    int hbase = hg * 4;

    precompute_scalars(b, nc, hbase, alpha, omega, dt, beta, rg, V, sA, sC1);
    __syncthreads();

    int wi   = threadIdx.x >> 5;
    int lane = threadIdx.x & 31;
    int h    = hbase + wi;
    bool lo16 = (lane < 16);

    float S0[4] = {0.f, 0.f, 0.f, 0.f};
    float S1[4] = {0.f, 0.f, 0.f, 0.f};
    float Ax = 1.f, Ay = 0.f;                 // cumA as complex scalar

    const float4* Kp = (const float4*)K + ((b * L_ + nc * C_) * H_ + h) * (D_ / 4) + lane;
    const int kstride = H_ * (D_ / 4);

    // -------- Phase A: intra-chunk scan (folded 7-shfl reduction) --------
    #pragma unroll 4
    for (int t = 0; t < C_; t++) {
        float4 kv = Kp[t * kstride];
        float4 sc = sA[wi * C_ + t];     // {a11, a12, beta, bdt*v0}
        float  c1 = sC1[wi * C_ + t];

        float p0 = S0[0]*kv.x + S0[1]*kv.y + S0[2]*kv.z + S0[3]*kv.w;
        float p1 = S1[0]*kv.x + S1[1]*kv.y + S1[2]*kv.z + S1[3]*kv.w;

        // folded warp reduction: p0 -> lanes 0-15, p1 -> lanes 16-31
        float xa = __shfl_xor_sync(0xffffffffu, p0, 16);
        float xb = __shfl_xor_sync(0xffffffffu, p1, 16);
        float m  = lo16 ? (p0 + xa) : (p1 + xb);
        m += __shfl_xor_sync(0xffffffffu, m, 8);
        m += __shfl_xor_sync(0xffffffffu, m, 4);
        m += __shfl_xor_sync(0xffffffffu, m, 2);
        m += __shfl_xor_sync(0xffffffffu, m, 1);
        float other = __shfl_xor_sync(0xffffffffu, m, 16);
        float tot0 = lo16 ? m : other;
        float tot1 = lo16 ? other : m;

        // u_t = w_t - beta * (c_t o phi)
        float bd0 = sc.x * tot0 + sc.y * tot1;
        float bd1 = sc.x * tot1 - sc.y * tot0;
        float u0  = sc.w - sc.z * bd0;
        float u1  = c1   - sc.z * bd1;

        float kk[4] = {kv.x, kv.y, kv.z, kv.w};
        #pragma unroll
        for (int j = 0; j < 4; j++) {
            float o0 = S0[j];
            S0[j] = sc.x * S0[j] + sc.y * S1[j] + u0 * kk[j];
            S1[j] = sc.x * S1[j] - sc.y * o0    + u1 * kk[j];
        }
        float nAx = sc.x * Ax - sc.y * Ay;
        float nAy = sc.x * Ay + sc.y * Ax;
        Ax = nAx; Ay = nAy;

        if (lane == 0) sU[wi][t] = make_float2(u0, u1);
    }
    __syncwarp();

    // -------- Publish local + decoupled lookback (per warp) --------
    int gidx = (b * NC_ + nc) * H_ + h;
    float E0[4] = {0.f, 0.f, 0.f, 0.f};
    float E1[4] = {0.f, 0.f, 0.f, 0.f};

    if (nc > 0) {
        float4* lh = (float4*)&g_loc_h[gidx * 2 * D_];
        lh[lane]      = make_float4(S0[0], S0[1], S0[2], S0[3]);
        lh[32 + lane] = make_float4(S1[0], S1[1], S1[2], S1[3]);
        if (lane == 0) g_loc_A[gidx] = make_float2(Ax, Ay);
        __threadfence();
        if (lane == 0) st_release(&g_flag[gidx], 1);

        float cAx = 1.f, cAy = 0.f;
        int j = nc - 1;
        while (true) {
            int jidx = (b * NC_ + j) * H_ + h;
            int f;
            do { f = ld_acquire(&g_flag[jidx]); } while (f == 0);
            f = (int)__reduce_min_sync(0xffffffffu, (unsigned)f);

            const float4* src = (const float4*)((f == 2) ? &g_inc_h[jidx * 2 * D_]
                                                         : &g_loc_h[jidx * 2 * D_]);
            float4 a0 = src[lane];
            float4 a1 = src[32 + lane];
            // E += cA o a
            E0[0] += cAx * a0.x + cAy * a1.x;  E1[0] += cAx * a1.x - cAy * a0.x;
            E0[1] += cAx * a0.y + cAy * a1.y;  E1[1] += cAx * a1.y - cAy * a0.y;
            E0[2] += cAx * a0.z + cAy * a1.z;  E1[2] += cAx * a1.z - cAy * a0.z;
            E0[3] += cAx * a0.w + cAy * a1.w;  E1[3] += cAx * a1.w - cAy * a0.w;

            if (f == 2) break;            // j==0 always publishes inclusive
            float2 Aj = g_loc_A[jidx];
            float nx = cAx * Aj.x - cAy * Aj.y;
            float ny = cAx * Aj.y + cAy * Aj.x;
            cAx = nx; cAy = ny;
            j--;
        }
    }

    // -------- Publish inclusive: I = A_self o E + S --------
    {
        float4* ih = (float4*)&g_inc_h[gidx * 2 * D_];
        float4 i0, i1;
        i0.x = Ax*E0[0] + Ay*E1[0] + S0[0];  i1.x = Ax*E1[0] - Ay*E0[0] + S1[0];
        i0.y = Ax*E0[1] + Ay*E1[1] + S0[1];  i1.y = Ax*E1[1] - Ay*E0[1] + S1[1];
        i0.z = Ax*E0[2] + Ay*E1[2] + S0[2];  i1.z = Ax*E1[2] - Ay*E0[2] + S1[2];
        i0.w = Ax*E0[3] + Ay*E1[3] + S0[3];  i1.w = Ax*E1[3] - Ay*E0[3] + S1[3];
        ih[lane]      = i0;
        ih[32 + lane] = i1;
        __threadfence();
        if (lane == 0) st_release(&g_flag[gidx], 2);
    }

    // -------- chunk_states output: state ENTERING this chunk = E --------
    {
        float4* sp = (float4*)&states[gidx * 2 * D_];
        sp[lane]      = make_float4(E0[0], E0[1], E0[2], E0[3]);
        sp[32 + lane] = make_float4(E1[0], E1[1], E1[2], E1[3]);
    }

    // -------- Phase 2: Y output. z_t = c_t o z_{t-1} + u_t k_t --------
    float4* Yp = (float4*)&Y[(((b * L_ + nc * C_) * H_ + h) * 2) * D_] + lane;
    const int ystride = H_ * 2 * (D_ / 4);

    #pragma unroll 4
    for (int t = 0; t < C_; t++) {
        float4 kv = Kp[t * kstride];
        float4 sc = sA[wi * C_ + t];
        float2 u  = sU[wi][t];

        float kk[4] = {kv.x, kv.y, kv.z, kv.w};
        #pragma unroll
        for (int j = 0; j < 4; j++) {
            float o0 = E0[j];
            E0[j] = sc.x * E0[j] + sc.y * E1[j] + u.x * kk[j];
            E1[j] = sc.x * E1[j] - sc.y * o0    + u.y * kk[j];
        }
        __stcs(&Yp[t * ystride],            make_float4(E0[0], E0[1], E0[2], E0[3]));
        __stcs(&Yp[t * ystride + D_ / 4],   make_float4(E1[0], E1[1], E1[2], E1[3]));
    }
}

// ---------------------------------------------------------------------------
extern "C" void kernel_launch(void* const* d_in, const int* in_sizes, int n_in,
                              void* d_out, int out_size)
{
    const float* alpha = (const float*)d_in[0];
    const float* omega = (const float*)d_in[1];
    const float* dt    = (const float*)d_in[2];
    const float* K     = (const float*)d_in[3];
    const float* V     = (const float*)d_in[4];
    const float* beta  = (const float*)d_in[5];
    const float* rg    = (const float*)d_in[6];

    float* Y      = (float*)d_out;                       // (B,L,H,2,D)
    float* states = Y + (size_t)B_ * L_ * H_ * 2 * D_;   // (B,NC,H,2,D)

    k_clear<<<8, 512>>>();
    k_fused<<<B_ * NC_ * (H_ / 4), 128>>>(alpha, omega, dt, K, V, beta, rg, Y, states);
}

// round 5
// speedup vs baseline: 1.1049x; 1.0351x over previous
#include <cuda_runtime.h>

#define B_  4
#define L_  4096
#define H_  16
#define D_  128
#define C_  64
#define NC_ 64
#define GATING_Cf 8.0f

// Scratch (allocation-free rule: __device__ globals)
__device__ float g_final_h[B_ * NC_ * H_ * 2 * D_];   // (b,nc,h,s,d)
__device__ float g_total_A[B_ * NC_ * H_ * 4];        // (b,nc,h,{a00,a01,a10,a11})
__device__ float g_u[B_ * NC_ * H_ * C_ * 2];         // (b,nc,h,t,{u0,u1})

// ---- f32x2 packed-math helpers (FFMA2: PTX-only on sm_103a) ----
typedef unsigned long long u64t;
__device__ __forceinline__ u64t pk2(float lo, float hi) {
    u64t r; asm("mov.b64 %0,{%1,%2};" : "=l"(r) : "f"(lo), "f"(hi)); return r;
}
__device__ __forceinline__ float2 up2(u64t v) {
    float2 f; asm("mov.b64 {%0,%1},%2;" : "=f"(f.x), "=f"(f.y) : "l"(v)); return f;
}
__device__ __forceinline__ u64t ffma2(u64t a, u64t b, u64t c) {
    u64t d; asm("fma.rn.f32x2 %0,%1,%2,%3;" : "=l"(d) : "l"(a), "l"(b), "l"(c)); return d;
}
__device__ __forceinline__ u64t fmul2(u64t a, u64t b) {
    u64t d; asm("mul.rn.f32x2 %0,%1,%2;" : "=l"(d) : "l"(a), "l"(b)); return d;
}

// ---------------------------------------------------------------------------
// Per-timestep scalar precompute (Cayley discretization + gate modulation).
// sA[wi*64+t] = {a11, a12, beta, beta*dt*v0}; sC1[wi*64+t] = beta*dt*v1
// ---------------------------------------------------------------------------
__device__ __forceinline__ void precompute_scalars(
    int b, int nc, int hbase,
    const float* __restrict__ alpha, const float* __restrict__ omega,
    const float* __restrict__ dt,    const float* __restrict__ beta,
    const float* __restrict__ rg,    const float* __restrict__ V,
    float4* sA, float* sC1)
{
    for (int q = threadIdx.x; q < 4 * C_; q += blockDim.x) {
        int wi = q >> 6;
        int t  = q & 63;
        int h  = hbase + wi;
        int l  = nc * C_ + t;
        int idx = (b * L_ + l) * H_ + h;

        float al  = alpha[idx];
        float om  = omega[idx];
        float dtt = dt[idx];
        float be  = beta[idx];
        float r   = rg[idx];

        float tau = 0.5f * dtt;
        float ta  = tau * al;
        float to  = tau * om;
        float opa = 1.0f + ta;
        float oma = 1.0f - ta;
        float to2 = to * to;

        float den   = opa * opa + to2 + 1e-6f;
        float invd  = 1.0f / den;
        float a11   = (opa * oma - to2) * invd;
        float a12   = 2.0f * to * invd;

        float numer = oma * oma + to2;
        float den_e = opa * opa + to2;
        float eig   = numer / (den_e + 1e-6f);
        float expo  = (GATING_Cf * r - 1.0f) * 0.5f;
        float scale = exp2f(expo * __log2f(fmaxf(eig, 1e-8f)));
        a11 *= scale;
        a12 *= scale;

        float v0  = V[idx * 2 + 0];
        float v1  = V[idx * 2 + 1];
        float bdt = be * dtt;

        sA[q]  = make_float4(a11, a12, be, bdt * v0);
        sC1[q] = bdt * v1;
    }
}

// Lightweight variant for k_full: only (a11, a12) needed.
__device__ __forceinline__ void precompute_c_only(
    int b, int nc, int hbase,
    const float* __restrict__ alpha, const float* __restrict__ omega,
    const float* __restrict__ dt,    const float* __restrict__ rg,
    float2* sC)
{
    for (int q = threadIdx.x; q < 4 * C_; q += blockDim.x) {
        int wi = q >> 6;
        int t  = q & 63;
        int h  = hbase + wi;
        int l  = nc * C_ + t;
        int idx = (b * L_ + l) * H_ + h;

        float al  = alpha[idx];
        float om  = omega[idx];
        float dtt = dt[idx];
        float r   = rg[idx];

        float tau = 0.5f * dtt;
        float ta  = tau * al;
        float to  = tau * om;
        float opa = 1.0f + ta;
        float oma = 1.0f - ta;
        float to2 = to * to;

        float den   = opa * opa + to2 + 1e-6f;
        float invd  = 1.0f / den;
        float a11   = (opa * oma - to2) * invd;
        float a12   = 2.0f * to * invd;

        float numer = oma * oma + to2;
        float den_e = opa * opa + to2;
        float eig   = numer / (den_e + 1e-6f);
        float expo  = (GATING_Cf * r - 1.0f) * 0.5f;
        float scale = exp2f(expo * __log2f(fmaxf(eig, 1e-8f)));

        sC[q] = make_float2(a11 * scale, a12 * scale);
    }
}

// ---------------------------------------------------------------------------
// K1: intra-chunk scan -> final_h, total_A (rotation scalar), u scalars.
// One warp per (b,nc,h); lane owns 4 d-slots packed as 2x f32x2.
// ---------------------------------------------------------------------------
__global__ __launch_bounds__(128, 8)
void k_intra(const float* __restrict__ alpha, const float* __restrict__ omega,
             const float* __restrict__ dt,    const float* __restrict__ K,
             const float* __restrict__ V,     const float* __restrict__ beta,
             const float* __restrict__ rg)
{
    __shared__ float4 sA[4 * C_];
    __shared__ float  sC1[4 * C_];
    __shared__ float2 sU[4][C_];

    int blk   = blockIdx.x;          // ((b*NC + nc)*4 + hg)
    int hg    = blk & 3;
    int bn    = blk >> 2;
    int nc    = bn % NC_;
    int b     = bn / NC_;
    int hbase = hg * 4;

    precompute_scalars(b, nc, hbase, alpha, omega, dt, beta, rg, V, sA, sC1);
    __syncthreads();

    int wi   = threadIdx.x >> 5;
    int lane = threadIdx.x & 31;
    int h    = hbase + wi;
    bool lo16 = (lane < 16);

    u64t S0a = 0, S0b = 0, S1a = 0, S1b = 0;   // packed state (4 d per lane)
    float Ax = 1.f, Ay = 0.f;                  // cumA as complex scalar

    const float4* Kp = (const float4*)K + ((b * L_ + nc * C_) * H_ + h) * (D_ / 4) + lane;
    const int kstride = H_ * (D_ / 4);

    #pragma unroll 4
    for (int t = 0; t < C_; t++) {
        float4 kv = Kp[t * kstride];
        float4 sc = sA[wi * C_ + t];     // {a11, a12, beta, bdt*v0}
        float  c1 = sC1[wi * C_ + t];

        u64t k01 = pk2(kv.x, kv.y);
        u64t k23 = pk2(kv.z, kv.w);

        float2 q0 = up2(ffma2(S0a, k01, fmul2(S0b, k23)));
        float2 q1 = up2(ffma2(S1a, k01, fmul2(S1b, k23)));
        float p0 = q0.x + q0.y;
        float p1 = q1.x + q1.y;

        // folded warp reduction: p0 -> lanes 0-15, p1 -> lanes 16-31
        float xa = __shfl_xor_sync(0xffffffffu, p0, 16);
        float xb = __shfl_xor_sync(0xffffffffu, p1, 16);
        float m  = lo16 ? (p0 + xa) : (p1 + xb);
        m += __shfl_xor_sync(0xffffffffu, m, 8);
        m += __shfl_xor_sync(0xffffffffu, m, 4);
        m += __shfl_xor_sync(0xffffffffu, m, 2);
        m += __shfl_xor_sync(0xffffffffu, m, 1);
        float other = __shfl_xor_sync(0xffffffffu, m, 16);
        float tot0 = lo16 ? m : other;
        float tot1 = lo16 ? other : m;

        // u_t = w_t - beta * (c_t o phi)
        float bd0 = sc.x * tot0 + sc.y * tot1;
        float bd1 = sc.x * tot1 - sc.y * tot0;
        float u0  = sc.w - sc.z * bd0;
        float u1  = c1   - sc.z * bd1;

        u64t cx2  = pk2(sc.x,  sc.x);
        u64t cy2  = pk2(sc.y,  sc.y);
        u64t ncy2 = pk2(-sc.y, -sc.y);
        u64t u02  = pk2(u0, u0);
        u64t u12  = pk2(u1, u1);

        u64t oS0a = S0a, oS0b = S0b;
        S0a = ffma2(cx2, S0a, ffma2(cy2, S1a, fmul2(u02, k01)));
        S0b = ffma2(cx2, S0b, ffma2(cy2, S1b, fmul2(u02, k23)));
        S1a = ffma2(cx2, S1a, ffma2(ncy2, oS0a, fmul2(u12, k01)));
        S1b = ffma2(cx2, S1b, ffma2(ncy2, oS0b, fmul2(u12, k23)));

        float nAx = sc.x * Ax - sc.y * Ay;
        float nAy = sc.x * Ay + sc.y * Ax;
        Ax = nAx; Ay = nAy;

        if (lane == 0) sU[wi][t] = make_float2(u0, u1);
    }

    float2 s0a = up2(S0a), s0b = up2(S0b), s1a = up2(S1a), s1b = up2(S1b);
    int base = (((b * NC_ + nc) * H_ + h) * 2) * D_;
    ((float4*)&g_final_h[base])[lane]      = make_float4(s0a.x, s0a.y, s0b.x, s0b.y);
    ((float4*)&g_final_h[base + D_])[lane] = make_float4(s1a.x, s1a.y, s1b.x, s1b.y);
    if (lane == 0)
        ((float4*)g_total_A)[(b * NC_ + nc) * H_ + h] = make_float4(Ax, Ay, -Ay, Ax);

    __syncwarp();
    // coalesced u writeback: 64 t * 2 floats = 32 float4 per warp
    float4* ug = (float4*)&g_u[(((b * NC_ + nc) * H_ + h) * C_) * 2];
    ug[lane] = ((const float4*)sU[wi])[lane];
}

// ---------------------------------------------------------------------------
// K2: inter-chunk serial scan. One block per (b,h), thread = d.
// Emits the PRE-update state (state entering chunk nc).
// ---------------------------------------------------------------------------
__global__ __launch_bounds__(128)
void k_inter(float* __restrict__ out_states)
{
    int b = blockIdx.x >> 4;
    int h = blockIdx.x & 15;
    int d = threadIdx.x;

    float s0 = 0.f, s1 = 0.f;

    float4 a  = ((const float4*)g_total_A)[(b * NC_ + 0) * H_ + h];
    int fb    = (((b * NC_ + 0) * H_ + h) * 2) * D_;
    float f0  = g_final_h[fb + d];
    float f1  = g_final_h[fb + D_ + d];

    for (int nc = 0; nc < NC_; nc++) {
        float4 an = make_float4(0.f, 0.f, 0.f, 0.f);
        float f0n = 0.f, f1n = 0.f;
        if (nc + 1 < NC_) {
            an = ((const float4*)g_total_A)[(b * NC_ + nc + 1) * H_ + h];
            int fb2 = (((b * NC_ + nc + 1) * H_ + h) * 2) * D_;
            f0n = g_final_h[fb2 + d];
            f1n = g_final_h[fb2 + D_ + d];
        }
        int ob = (((b * NC_ + nc) * H_ + h) * 2) * D_;
        out_states[ob + d]       = s0;
        out_states[ob + D_ + d]  = s1;

        float ns0 = a.x * s0 + a.y * s1 + f0;
        float ns1 = a.z * s0 + a.w * s1 + f1;
        s0 = ns0; s1 = ns1;
        a = an; f0 = f0n; f1 = f1n;
    }
}

// ---------------------------------------------------------------------------
// K3: output pass, D split across 2 warps per (b,nc,h) for 2x occupancy.
// 256 threads = 8 warps = 4 heads x 2 d-halves. Lane owns 2 complex comps.
// z_t = c_t o z_{t-1} + u_t k_t,  z_0 = chunk entering state; Y row t = z_t.
// ---------------------------------------------------------------------------
__global__ __launch_bounds__(256, 7)
void k_full(const float* __restrict__ alpha, const float* __restrict__ omega,
            const float* __restrict__ dt,    const float* __restrict__ K,
            const float* __restrict__ rg,    const float* __restrict__ states,
            float* __restrict__ Y)
{
    __shared__ float2 sC[4 * C_];
    __shared__ float2 sU[4 * C_];

    int blk   = blockIdx.x;          // ((b*NC + nc)*4 + hg)
    int hg    = blk & 3;
    int bn    = blk >> 2;
    int nc    = bn % NC_;
    int b     = bn / NC_;
    int hbase = hg * 4;

    precompute_c_only(b, nc, hbase, alpha, omega, dt, rg, sC);

    // load u for this block's 4 heads: 512 contiguous floats -> 128 float4
    if (threadIdx.x < 128) {
        const float4* ug = (const float4*)&g_u[(((b * NC_ + nc) * H_ + hbase) * C_) * 2];
        float4 v = ug[threadIdx.x];
        int hi = threadIdx.x >> 5;          // 32 float4 per head
        int t2 = (threadIdx.x & 31) * 2;
        sU[hi * C_ + t2]     = make_float2(v.x, v.y);
        sU[hi * C_ + t2 + 1] = make_float2(v.z, v.w);
    }
    __syncthreads();

    int w    = threadIdx.x >> 5;
    int lane = threadIdx.x & 31;
    int hi   = w >> 1;               // head within group
    int h    = hbase + hi;
    int dh   = (w & 1) * 64;         // d-half offset
    int ci   = hi * C_;

    // init z = chunk entering state (lane owns 2 complex components)
    int sb = (((b * NC_ + nc) * H_ + h) * 2) * D_ + dh + lane * 2;
    float2 z0 = *(const float2*)&states[sb];
    float2 z1 = *(const float2*)&states[sb + D_];

    const float2* Kp2 = (const float2*)(K + ((b * L_ + nc * C_) * H_ + h) * D_ + dh) + lane;
    const int ks2 = H_ * (D_ / 2);
    float2* Yp0 = (float2*)(Y + (((b * L_ + nc * C_) * H_ + h) * 2) * D_ + dh) + lane;
    float2* Yp1 = Yp0 + D_ / 2;
    const int ys2 = H_ * 2 * (D_ / 2);

    #pragma unroll 4
    for (int t = 0; t < C_; t++) {
        float2 kv = __ldcs(&Kp2[t * ks2]);
        float2 c  = sC[ci + t];
        float2 u  = sU[ci + t];

        float o0x = z0.x, o0y = z0.y;
        z0.x = fmaf(c.x, z0.x, fmaf(c.y, z1.x, u.x * kv.x));
        z0.y = fmaf(c.x, z0.y, fmaf(c.y, z1.y, u.x * kv.y));
        z1.x = fmaf(c.x, z1.x, fmaf(-c.y, o0x, u.y * kv.x));
        z1.y = fmaf(c.x, z1.y, fmaf(-c.y, o0y, u.y * kv.y));

        __stcs(&Yp0[t * ys2], z0);
        __stcs(&Yp1[t * ys2], z1);
    }
}

// ---------------------------------------------------------------------------
extern "C" void kernel_launch(void* const* d_in, const int* in_sizes, int n_in,
                              void* d_out, int out_size)
{
    const float* alpha = (const float*)d_in[0];
    const float* omega = (const float*)d_in[1];
    const float* dt    = (const float*)d_in[2];
    const float* K     = (const float*)d_in[3];
    const float* V     = (const float*)d_in[4];
    const float* beta  = (const float*)d_in[5];
    const float* rg    = (const float*)d_in[6];

    float* Y      = (float*)d_out;                       // (B,L,H,2,D)
    float* states = Y + (size_t)B_ * L_ * H_ * 2 * D_;   // (B,NC,H,2,D)

    k_intra<<<B_ * NC_ * (H_ / 4), 128>>>(alpha, omega, dt, K, V, beta, rg);
    k_inter<<<B_ * H_, 128>>>(states);
    k_full<<<B_ * NC_ * (H_ / 4), 256>>>(alpha, omega, dt, K, rg, states, Y);
}